// round 1
// baseline (speedup 1.0000x reference)
#include <cuda_runtime.h>
#include <cuda_bf16.h>

#define NEXP 8
#define TOPK 2
#define DIN  1024
#define DOUT 1024
#define NTOK 8192

#define BM 128
#define BN 128
#define BK 8

// ---- scratch (device globals: allocation-free per harness rules) ----
__device__ int   g_cnt[NEXP];                             // tokens routed per expert
__device__ int   g_tok[NEXP * NTOK];                      // token id per (expert, slot)
__device__ float g_wt [NEXP * NTOK];                      // gate weight per (expert, slot)
__device__ float g_h  [(size_t)NEXP * NTOK * DOUT];       // 256MB: relu(x@W1+b1) rows

// ---------------------------------------------------------------------------
// Zero output + expert counters (out is poisoned to 0xAA before timing).
// ---------------------------------------------------------------------------
__global__ void zero_kernel(float* __restrict__ out) {
    int i = blockIdx.x * blockDim.x + threadIdx.x;
    ((float4*)out)[i] = make_float4(0.f, 0.f, 0.f, 0.f);
    if (blockIdx.x == 0 && threadIdx.x < NEXP) g_cnt[threadIdx.x] = 0;
}

// ---------------------------------------------------------------------------
// Gating: one warp per token. logits = x@Wg + bg ; softmax ; top-2.
// Emits per-expert token lists + gate weights via atomic append.
// ---------------------------------------------------------------------------
__global__ void gate_kernel(const float* __restrict__ x,
                            const float* __restrict__ Wg,   // [DIN, NEXP]
                            const float* __restrict__ bg) { // [NEXP]
    int warp = (blockIdx.x * blockDim.x + threadIdx.x) >> 5;
    int lane = threadIdx.x & 31;
    if (warp >= NTOK) return;

    const float* xr = x + (size_t)warp * DIN;
    float acc[NEXP];
#pragma unroll
    for (int e = 0; e < NEXP; e++) acc[e] = 0.f;

    for (int kk = 0; kk < DIN / 32; kk++) {
        int k = kk * 32 + lane;
        float xv = xr[k];
        const float* wr = Wg + k * NEXP;
#pragma unroll
        for (int e = 0; e < NEXP; e++) acc[e] += xv * wr[e];
    }
#pragma unroll
    for (int e = 0; e < NEXP; e++) {
#pragma unroll
        for (int o = 16; o > 0; o >>= 1)
            acc[e] += __shfl_xor_sync(0xffffffffu, acc[e], o);
    }

    if (lane == 0) {
        float m = -1e30f;
#pragma unroll
        for (int e = 0; e < NEXP; e++) { acc[e] += bg[e]; m = fmaxf(m, acc[e]); }
        float s = 0.f;
#pragma unroll
        for (int e = 0; e < NEXP; e++) { acc[e] = expf(acc[e] - m); s += acc[e]; }
        float inv = 1.f / s;

        // top-2 (first occurrence wins ties, matching lax.top_k lowest-index)
        int e0 = 0, e1 = -1;
        float v0 = acc[0], v1 = -1.f;
#pragma unroll
        for (int e = 1; e < NEXP; e++) {
            float v = acc[e];
            if (v > v0)      { v1 = v0; e1 = e0; v0 = v; e0 = e; }
            else if (v > v1) { v1 = v;  e1 = e; }
        }
        int p0 = atomicAdd(&g_cnt[e0], 1);
        g_tok[e0 * NTOK + p0] = warp;  g_wt[e0 * NTOK + p0] = v0 * inv;
        int p1 = atomicAdd(&g_cnt[e1], 1);
        g_tok[e1 * NTOK + p1] = warp;  g_wt[e1 * NTOK + p1] = v1 * inv;
    }
}

// ---------------------------------------------------------------------------
// GEMM1: for expert e, h = relu( x[tokens_e] @ W1[e] + b1[e] )  (gathered A)
// 128x128 tile, BK=8, 256 threads, 8x8 microtile per thread.
// ---------------------------------------------------------------------------
__global__ __launch_bounds__(256, 2)
void gemm1_kernel(const float* __restrict__ x,
                  const float* __restrict__ W1,   // [E, DIN, DOUT]
                  const float* __restrict__ b1) { // [E, DOUT]
    int e   = blockIdx.z;
    int cnt = g_cnt[e];
    int m0  = blockIdx.y * BM;
    if (m0 >= cnt) return;
    int n0  = blockIdx.x * BN;

    __shared__ float As[BK][BM];
    __shared__ float Bs[BK][BN];

    int tid = threadIdx.x;
    int tx = tid & 15, ty = tid >> 4;

    // A load: thread -> (row ar, k-quad aq). Row gathered from token list.
    int ar = tid >> 1;
    int aq = (tid & 1) * 4;
    bool avalid = (m0 + ar) < cnt;
    const float* aptr = nullptr;
    if (avalid) {
        int t = g_tok[e * NTOK + m0 + ar];
        aptr = x + (size_t)t * DIN + aq;
    }
    // B load: thread -> (k row bk, n-quad bn)
    int bk = tid >> 5;
    int bn = (tid & 31) * 4;
    const float* bptr = W1 + (size_t)e * DIN * DOUT + (size_t)bk * DOUT + n0 + bn;

    float acc[8][8];
#pragma unroll
    for (int i = 0; i < 8; i++)
#pragma unroll
        for (int j = 0; j < 8; j++) acc[i][j] = 0.f;

    for (int k0 = 0; k0 < DIN; k0 += BK) {
        float4 av = make_float4(0.f, 0.f, 0.f, 0.f);
        if (avalid) av = *(const float4*)(aptr + k0);
        float4 bv = *(const float4*)(bptr + (size_t)k0 * DOUT);
        __syncthreads();
        As[aq + 0][ar] = av.x;  As[aq + 1][ar] = av.y;
        As[aq + 2][ar] = av.z;  As[aq + 3][ar] = av.w;
        *(float4*)&Bs[bk][bn] = bv;
        __syncthreads();
#pragma unroll
        for (int kk = 0; kk < BK; kk++) {
            float a[8], b[8];
            *(float4*)&a[0] = *(const float4*)&As[kk][ty * 8];
            *(float4*)&a[4] = *(const float4*)&As[kk][ty * 8 + 4];
            *(float4*)&b[0] = *(const float4*)&Bs[kk][tx * 8];
            *(float4*)&b[4] = *(const float4*)&Bs[kk][tx * 8 + 4];
#pragma unroll
            for (int i = 0; i < 8; i++)
#pragma unroll
                for (int j = 0; j < 8; j++)
                    acc[i][j] += a[i] * b[j];
        }
    }

#pragma unroll
    for (int i = 0; i < 8; i++) {
        int m = m0 + ty * 8 + i;
        if (m < cnt) {
            float* hrow = g_h + ((size_t)e * NTOK + m) * DOUT + n0 + tx * 8;
#pragma unroll
            for (int j = 0; j < 8; j++) {
                float v = acc[i][j] + b1[e * DOUT + n0 + tx * 8 + j];
                hrow[j] = fmaxf(v, 0.f);
            }
        }
    }
}

// ---------------------------------------------------------------------------
// GEMM2: y = h @ W2[e] + b2[e]; out[token] += gate_w * y  (atomic scatter).
// Each out element receives exactly 2 fp32 adds onto 0 -> order-independent.
// ---------------------------------------------------------------------------
__global__ __launch_bounds__(256, 2)
void gemm2_kernel(const float* __restrict__ W2,   // [E, DOUT, DOUT]
                  const float* __restrict__ b2,   // [E, DOUT]
                  float* __restrict__ out) {      // [NTOK, DOUT]
    int e   = blockIdx.z;
    int cnt = g_cnt[e];
    int m0  = blockIdx.y * BM;
    if (m0 >= cnt) return;
    int n0  = blockIdx.x * BN;

    __shared__ float As[BK][BM];
    __shared__ float Bs[BK][BN];

    int tid = threadIdx.x;
    int tx = tid & 15, ty = tid >> 4;

    int ar = tid >> 1;
    int aq = (tid & 1) * 4;
    bool avalid = (m0 + ar) < cnt;
    const float* aptr = g_h + ((size_t)e * NTOK + m0 + ar) * DOUT + aq;

    int bk = tid >> 5;
    int bn = (tid & 31) * 4;
    const float* bptr = W2 + (size_t)e * DOUT * DOUT + (size_t)bk * DOUT + n0 + bn;

    float acc[8][8];
#pragma unroll
    for (int i = 0; i < 8; i++)
#pragma unroll
        for (int j = 0; j < 8; j++) acc[i][j] = 0.f;

    for (int k0 = 0; k0 < DOUT; k0 += BK) {
        float4 av = make_float4(0.f, 0.f, 0.f, 0.f);
        if (avalid) av = *(const float4*)(aptr + k0);
        float4 bv = *(const float4*)(bptr + (size_t)k0 * DOUT);
        __syncthreads();
        As[aq + 0][ar] = av.x;  As[aq + 1][ar] = av.y;
        As[aq + 2][ar] = av.z;  As[aq + 3][ar] = av.w;
        *(float4*)&Bs[bk][bn] = bv;
        __syncthreads();
#pragma unroll
        for (int kk = 0; kk < BK; kk++) {
            float a[8], b[8];
            *(float4*)&a[0] = *(const float4*)&As[kk][ty * 8];
            *(float4*)&a[4] = *(const float4*)&As[kk][ty * 8 + 4];
            *(float4*)&b[0] = *(const float4*)&Bs[kk][tx * 8];
            *(float4*)&b[4] = *(const float4*)&Bs[kk][tx * 8 + 4];
#pragma unroll
            for (int i = 0; i < 8; i++)
#pragma unroll
                for (int j = 0; j < 8; j++)
                    acc[i][j] += a[i] * b[j];
        }
    }

#pragma unroll
    for (int i = 0; i < 8; i++) {
        int m = m0 + ty * 8 + i;
        if (m < cnt) {
            int   t = g_tok[e * NTOK + m];
            float w = g_wt [e * NTOK + m];
            float* orow = out + (size_t)t * DOUT + n0 + tx * 8;
#pragma unroll
            for (int j = 0; j < 8; j++) {
                float v = acc[i][j] + b2[e * DOUT + n0 + tx * 8 + j];
                atomicAdd(&orow[j], w * v);
            }
        }
    }
}

// ---------------------------------------------------------------------------
// kernel_launch — graph-capturable: kernel launches only, no sync, no alloc.
// Input order per reference setup_inputs: x, W1, b1, W2, b2, Wg, bg.
// ---------------------------------------------------------------------------
extern "C" void kernel_launch(void* const* d_in, const int* in_sizes, int n_in,
                              void* d_out, int out_size) {
    const float* x  = (const float*)d_in[0];
    const float* W1 = (const float*)d_in[1];
    const float* b1 = (const float*)d_in[2];
    const float* W2 = (const float*)d_in[3];
    const float* b2 = (const float*)d_in[4];
    const float* Wg = (const float*)d_in[5];
    const float* bg = (const float*)d_in[6];
    float* out = (float*)d_out;

    zero_kernel<<<(NTOK * DOUT) / 4 / 256, 256>>>(out);
    gate_kernel<<<(NTOK * 32) / 256, 256>>>(x, Wg, bg);

    dim3 grid(DOUT / BN, NTOK / BM, NEXP);
    gemm1_kernel<<<grid, 256>>>(x, W1, b1);
    gemm2_kernel<<<grid, 256>>>(W2, b2, out);
}

// round 3
// speedup vs baseline: 2.2318x; 2.2318x over previous
#include <cuda_runtime.h>
#include <cuda_bf16.h>
#include <cstdint>

#define NEXP 8
#define DIN  1024
#define DOUT 1024
#define NTOK 8192

#define BM 128
#define BN 128
#define BK 32
#define THREADS 256

#define ROWPITCH 80                    /* 32 bf16 = 64B data, padded to 80B */
#define TILE_B   (128 * ROWPITCH)      /* 10240 */
#define STAGE_B  (4 * TILE_B)          /* 40960: Ah, Al, Bh, Bl */
#define NSTAGE   3
#define SMEM_BYTES (NSTAGE * STAGE_B)  /* 122880 */

// ---------------- scratch (device globals; no allocation) ----------------
__device__ int   g_cnt[NEXP];
__device__ int   g_tok[NEXP * NTOK];
__device__ float g_wt [NEXP * NTOK];
__device__ __nv_bfloat16 g_xh [(size_t)NTOK * DIN];
__device__ __nv_bfloat16 g_xl [(size_t)NTOK * DIN];
__device__ __nv_bfloat16 g_hh [(size_t)NEXP * NTOK * DOUT];
__device__ __nv_bfloat16 g_hl [(size_t)NEXP * NTOK * DOUT];
__device__ __nv_bfloat16 g_W1Th[(size_t)NEXP * DIN * DOUT];
__device__ __nv_bfloat16 g_W1Tl[(size_t)NEXP * DIN * DOUT];
__device__ __nv_bfloat16 g_W2Th[(size_t)NEXP * DOUT * DOUT];
__device__ __nv_bfloat16 g_W2Tl[(size_t)NEXP * DOUT * DOUT];

// ---------------- helpers ----------------
__device__ __forceinline__ uint32_t smem_u32(const void* p) {
    uint32_t a;
    asm("{ .reg .u64 t; cvta.to.shared.u64 t, %1; cvt.u32.u64 %0, t; }" : "=r"(a) : "l"(p));
    return a;
}
__device__ __forceinline__ void cp_async16(uint32_t dst, const void* src) {
    asm volatile("cp.async.cg.shared.global [%0], [%1], 16;" :: "r"(dst), "l"(src) : "memory");
}
#define CP_COMMIT() asm volatile("cp.async.commit_group;" ::: "memory")
#define CP_WAIT1()  asm volatile("cp.async.wait_group 1;" ::: "memory")

__device__ __forceinline__ void mma_bf16(float* d, const uint32_t* a, const uint32_t* b) {
    asm volatile(
        "mma.sync.aligned.m16n8k16.row.col.f32.bf16.bf16.f32 "
        "{%0,%1,%2,%3},{%4,%5,%6,%7},{%8,%9},{%0,%1,%2,%3};"
        : "+f"(d[0]), "+f"(d[1]), "+f"(d[2]), "+f"(d[3])
        : "r"(a[0]), "r"(a[1]), "r"(a[2]), "r"(a[3]), "r"(b[0]), "r"(b[1]));
}

// ---------------------------------------------------------------------------
__global__ void zero_kernel(float* __restrict__ out) {
    int i = blockIdx.x * blockDim.x + threadIdx.x;
    ((float4*)out)[i] = make_float4(0.f, 0.f, 0.f, 0.f);
    if (blockIdx.x == 0 && threadIdx.x < NEXP) g_cnt[threadIdx.x] = 0;
}

// ---------------------------------------------------------------------------
__global__ void gate_kernel(const float* __restrict__ x,
                            const float* __restrict__ Wg,
                            const float* __restrict__ bg) {
    int warp = (blockIdx.x * blockDim.x + threadIdx.x) >> 5;
    int lane = threadIdx.x & 31;
    if (warp >= NTOK) return;
    const float* xr = x + (size_t)warp * DIN;
    float acc[NEXP];
#pragma unroll
    for (int e = 0; e < NEXP; e++) acc[e] = 0.f;
    for (int kk = 0; kk < DIN / 32; kk++) {
        int k = kk * 32 + lane;
        float xv = xr[k];
        const float* wr = Wg + k * NEXP;
#pragma unroll
        for (int e = 0; e < NEXP; e++) acc[e] += xv * wr[e];
    }
#pragma unroll
    for (int e = 0; e < NEXP; e++)
#pragma unroll
        for (int o = 16; o > 0; o >>= 1)
            acc[e] += __shfl_xor_sync(0xffffffffu, acc[e], o);
    if (lane == 0) {
        float m = -1e30f;
#pragma unroll
        for (int e = 0; e < NEXP; e++) { acc[e] += bg[e]; m = fmaxf(m, acc[e]); }
        float s = 0.f;
#pragma unroll
        for (int e = 0; e < NEXP; e++) { acc[e] = expf(acc[e] - m); s += acc[e]; }
        float inv = 1.f / s;
        int e0 = 0, e1 = -1;
        float v0 = acc[0], v1 = -1.f;
#pragma unroll
        for (int e = 1; e < NEXP; e++) {
            float v = acc[e];
            if (v > v0)      { v1 = v0; e1 = e0; v0 = v; e0 = e; }
            else if (v > v1) { v1 = v;  e1 = e; }
        }
        int p0 = atomicAdd(&g_cnt[e0], 1);
        g_tok[e0 * NTOK + p0] = warp;  g_wt[e0 * NTOK + p0] = v0 * inv;
        int p1 = atomicAdd(&g_cnt[e1], 1);
        g_tok[e1 * NTOK + p1] = warp;  g_wt[e1 * NTOK + p1] = v1 * inv;
    }
}

// ---------------------------------------------------------------------------
// x fp32 -> bf16 hi/lo split
// ---------------------------------------------------------------------------
__global__ void split_x_kernel(const float* __restrict__ x) {
    size_t i = ((size_t)blockIdx.x * blockDim.x + threadIdx.x) * 4;
    float4 v = *(const float4*)(x + i);
    __nv_bfloat16 h0 = __float2bfloat16(v.x), h1 = __float2bfloat16(v.y);
    __nv_bfloat16 h2 = __float2bfloat16(v.z), h3 = __float2bfloat16(v.w);
    __nv_bfloat16 l0 = __float2bfloat16(v.x - __bfloat162float(h0));
    __nv_bfloat16 l1 = __float2bfloat16(v.y - __bfloat162float(h1));
    __nv_bfloat16 l2 = __float2bfloat16(v.z - __bfloat162float(h2));
    __nv_bfloat16 l3 = __float2bfloat16(v.w - __bfloat162float(h3));
    *(__nv_bfloat162*)(g_xh + i)     = __halves2bfloat162(h0, h1);
    *(__nv_bfloat162*)(g_xh + i + 2) = __halves2bfloat162(h2, h3);
    *(__nv_bfloat162*)(g_xl + i)     = __halves2bfloat162(l0, l1);
    *(__nv_bfloat162*)(g_xl + i + 2) = __halves2bfloat162(l2, l3);
}

// ---------------------------------------------------------------------------
// W [E,K,N] fp32 -> W^T [E,N,K] bf16 hi/lo (fused transpose + split)
// ---------------------------------------------------------------------------
__global__ void transpose_split_kernel(const float* __restrict__ W,
                                       __nv_bfloat16* __restrict__ WTh,
                                       __nv_bfloat16* __restrict__ WTl) {
    __shared__ float t[32][33];
    int e = blockIdx.z;
    const float* Ws = W + ((size_t)e << 20);
    int x0 = blockIdx.x * 32, y0 = blockIdx.y * 32;
    int tx = threadIdx.x, ty = threadIdx.y;
#pragma unroll
    for (int i = 0; i < 32; i += 8)
        t[ty + i][tx] = Ws[(size_t)(y0 + ty + i) * 1024 + x0 + tx];
    __syncthreads();
#pragma unroll
    for (int i = 0; i < 32; i += 8) {
        float v = t[tx][ty + i];
        __nv_bfloat16 h = __float2bfloat16(v);
        __nv_bfloat16 l = __float2bfloat16(v - __bfloat162float(h));
        size_t o = ((size_t)e << 20) + (size_t)(x0 + ty + i) * 1024 + y0 + tx;
        WTh[o] = h;  WTl[o] = l;
    }
}

// ---------------------------------------------------------------------------
// bf16-split mma.sync GEMM: 128x128x32 tiles, 3-stage cp.async pipeline.
// 8 warps as 2(M) x 4(N); warp tile 64x32; mma.m16n8k16; 3 split terms.
// G2=false: A = gathered x rows (hi/lo), epi relu(D+b1) -> g_hh/g_hl
// G2=true : A = g_hh/g_hl slots,          epi out += w*(D+b2) atomics
// ---------------------------------------------------------------------------
template <bool G2>
__global__ __launch_bounds__(THREADS, 1)
void moe_mma_kernel(const __nv_bfloat16* __restrict__ Wh,
                    const __nv_bfloat16* __restrict__ Wl,
                    const float* __restrict__ bias,
                    float* __restrict__ outp) {
    extern __shared__ char smem[];
    __shared__ int   s_tok[128];
    __shared__ float s_wt[128];
    __shared__ float s_bias[128];

    const int e   = blockIdx.z;
    const int cnt = g_cnt[e];
    const int m0  = blockIdx.y * BM;
    if (m0 >= cnt) return;
    const int n0  = blockIdx.x * BN;

    const int tid  = threadIdx.x;
    const int wid  = tid >> 5;
    const int lane = tid & 31;

    if (tid < 128) {
        int ok = (m0 + tid) < cnt;
        s_tok[tid] = ok ? g_tok[e * NTOK + m0 + tid] : 0;
        s_wt[tid]  = ok ? g_wt[e * NTOK + m0 + tid] : 0.f;
        s_bias[tid] = bias[e * 1024 + n0 + tid];
    }
    __syncthreads();

    // ---- per-thread cp.async geometry: tile = tid>>6 (Ah,Al,Bh,Bl) ----
    const int tile = tid >> 6;
    const int l64  = tid & 63;
    const int ch   = l64 & 3;            // 16B chunk within 64B row
    const __nv_bfloat16* gsrc[8];
    uint32_t sdst[8];
    const uint32_t sb = smem_u32(smem);
#pragma unroll
    for (int i = 0; i < 8; i++) {
        int r = i * 16 + (l64 >> 2);     // row 0..127
        const __nv_bfloat16* base;
        size_t rowidx;
        if (tile < 2) {
            if (G2) {
                base = tile ? g_hl : g_hh;
                rowidx = (size_t)e * NTOK + (size_t)((m0 + r < cnt) ? (m0 + r) : m0);
            } else {
                base = tile ? g_xl : g_xh;
                rowidx = (size_t)s_tok[r];
            }
        } else {
            base = (tile == 3) ? Wl : Wh;
            rowidx = ((size_t)e << 10) * 1024 / 1024 * 1024;  // placeholder, fixed below
            rowidx = ((size_t)e << 20) / 1024 + (size_t)(n0 + r);  // row units of 1024
        }
        gsrc[i] = base + rowidx * 1024 + ch * 8;
        sdst[i] = sb + tile * TILE_B + r * ROWPITCH + ch * 16;
    }

    auto issue = [&](int s, int c) {
        uint32_t so = (uint32_t)(s * STAGE_B);
        size_t ko = (size_t)c * BK;
#pragma unroll
        for (int i = 0; i < 8; i++)
            cp_async16(sdst[i] + so, gsrc[i] + ko);
    };

    float acc[4][4][4];
#pragma unroll
    for (int a = 0; a < 4; a++)
#pragma unroll
        for (int b = 0; b < 4; b++)
#pragma unroll
            for (int c = 0; c < 4; c++) acc[a][b][c] = 0.f;

    issue(0, 0); CP_COMMIT();
    issue(1, 1); CP_COMMIT();

    const int wm = wid >> 2;             // 0..1 -> m offset 64*wm
    const int wn = wid & 3;              // 0..3 -> n offset 32*wn
    const int lr = lane >> 2;            // 0..7
    const int lq = (lane & 3) * 4;       // byte offset within k16 half

    const int NITER = DIN / BK;          // 32
    for (int c = 0; c < NITER; c++) {
        const int s = c % NSTAGE;
        CP_WAIT1();
        __syncthreads();
        if (c + 2 < NITER) issue((c + 2) % NSTAGE, c + 2);
        CP_COMMIT();

        const char* Ah = smem + s * STAGE_B;
        const char* Al = Ah + TILE_B;
        const char* Bh = Ah + 2 * TILE_B;
        const char* Bl = Ah + 3 * TILE_B;

#pragma unroll
        for (int ks = 0; ks < 2; ks++) {
            uint32_t ah[4][4], al[4][4], bh[4][2], bl[4][2];
#pragma unroll
            for (int mf = 0; mf < 4; mf++) {
                int off = (wm * 64 + mf * 16 + lr) * ROWPITCH + ks * 32 + lq;
                ah[mf][0] = *(const uint32_t*)(Ah + off);
                ah[mf][1] = *(const uint32_t*)(Ah + off + 8 * ROWPITCH);
                ah[mf][2] = *(const uint32_t*)(Ah + off + 16);
                ah[mf][3] = *(const uint32_t*)(Ah + off + 8 * ROWPITCH + 16);
                al[mf][0] = *(const uint32_t*)(Al + off);
                al[mf][1] = *(const uint32_t*)(Al + off + 8 * ROWPITCH);
                al[mf][2] = *(const uint32_t*)(Al + off + 16);
                al[mf][3] = *(const uint32_t*)(Al + off + 8 * ROWPITCH + 16);
            }
#pragma unroll
            for (int nf = 0; nf < 4; nf++) {
                int off = (wn * 32 + nf * 8 + lr) * ROWPITCH + ks * 32 + lq;
                bh[nf][0] = *(const uint32_t*)(Bh + off);
                bh[nf][1] = *(const uint32_t*)(Bh + off + 16);
                bl[nf][0] = *(const uint32_t*)(Bl + off);
                bl[nf][1] = *(const uint32_t*)(Bl + off + 16);
            }
#pragma unroll
            for (int mf = 0; mf < 4; mf++)
#pragma unroll
                for (int nf = 0; nf < 4; nf++)
                    mma_bf16(acc[mf][nf], ah[mf], bh[nf]);
#pragma unroll
            for (int mf = 0; mf < 4; mf++)
#pragma unroll
                for (int nf = 0; nf < 4; nf++)
                    mma_bf16(acc[mf][nf], ah[mf], bl[nf]);
#pragma unroll
            for (int mf = 0; mf < 4; mf++)
#pragma unroll
                for (int nf = 0; nf < 4; nf++)
                    mma_bf16(acc[mf][nf], al[mf], bh[nf]);
        }
    }

    // ---- epilogue: direct from registers (quads cover full 32B sectors) ----
    const int lc = (lane & 3) * 2;
#pragma unroll
    for (int mf = 0; mf < 4; mf++) {
#pragma unroll
        for (int nf = 0; nf < 4; nf++) {
            const float* d = acc[mf][nf];
            int col_l = wn * 32 + nf * 8 + lc;
            int colg  = n0 + col_l;
            float bb0 = s_bias[col_l], bb1 = s_bias[col_l + 1];
#pragma unroll
            for (int half = 0; half < 2; half++) {
                int row = wm * 64 + mf * 16 + lr + half * 8;  // local slot
                if (m0 + row >= cnt) continue;
                float v0 = d[half * 2]     + bb0;
                float v1 = d[half * 2 + 1] + bb1;
                if (!G2) {
                    v0 = fmaxf(v0, 0.f);  v1 = fmaxf(v1, 0.f);
                    __nv_bfloat16 h0 = __float2bfloat16(v0);
                    __nv_bfloat16 h1 = __float2bfloat16(v1);
                    __nv_bfloat16 l0 = __float2bfloat16(v0 - __bfloat162float(h0));
                    __nv_bfloat16 l1 = __float2bfloat16(v1 - __bfloat162float(h1));
                    size_t base = ((size_t)e * NTOK + m0 + row) * 1024 + colg;
                    *(__nv_bfloat162*)(g_hh + base) = __halves2bfloat162(h0, h1);
                    *(__nv_bfloat162*)(g_hl + base) = __halves2bfloat162(l0, l1);
                } else {
                    float w = s_wt[row];
                    float* o = outp + (size_t)s_tok[row] * 1024 + colg;
                    atomicAdd(o,     w * v0);
                    atomicAdd(o + 1, w * v1);
                }
            }
        }
    }
}

// ---------------------------------------------------------------------------
extern "C" void kernel_launch(void* const* d_in, const int* in_sizes, int n_in,
                              void* d_out, int out_size) {
    const float* x  = (const float*)d_in[0];
    const float* W1 = (const float*)d_in[1];
    const float* b1 = (const float*)d_in[2];
    const float* W2 = (const float*)d_in[3];
    const float* b2 = (const float*)d_in[4];
    const float* Wg = (const float*)d_in[5];
    const float* bg = (const float*)d_in[6];
    float* out = (float*)d_out;

    cudaFuncSetAttribute(moe_mma_kernel<false>,
                         cudaFuncAttributeMaxDynamicSharedMemorySize, SMEM_BYTES);
    cudaFuncSetAttribute(moe_mma_kernel<true>,
                         cudaFuncAttributeMaxDynamicSharedMemorySize, SMEM_BYTES);

    __nv_bfloat16 *w1th, *w1tl, *w2th, *w2tl;
    cudaGetSymbolAddress((void**)&w1th, g_W1Th);
    cudaGetSymbolAddress((void**)&w1tl, g_W1Tl);
    cudaGetSymbolAddress((void**)&w2th, g_W2Th);
    cudaGetSymbolAddress((void**)&w2tl, g_W2Tl);

    zero_kernel<<<(NTOK * DOUT) / 4 / 256, 256>>>(out);
    gate_kernel<<<(NTOK * 32) / 256, 256>>>(x, Wg, bg);
    split_x_kernel<<<(NTOK * DIN) / 4 / 256, 256>>>(x);

    dim3 tg(32, 32, NEXP);
    transpose_split_kernel<<<tg, dim3(32, 8)>>>(W1, w1th, w1tl);
    transpose_split_kernel<<<tg, dim3(32, 8)>>>(W2, w2th, w2tl);

    dim3 grid(DOUT / BN, NTOK / BM, NEXP);
    moe_mma_kernel<false><<<grid, THREADS, SMEM_BYTES>>>(w1th, w1tl, b1, nullptr);
    moe_mma_kernel<true><<<grid, THREADS, SMEM_BYTES>>>(w2th, w2tl, b2, out);
}

// round 4
// speedup vs baseline: 2.3316x; 1.0447x over previous
#include <cuda_runtime.h>
#include <cuda_bf16.h>
#include <cstdint>

#define NEXP 8
#define DIN  1024
#define DOUT 1024
#define NTOK 8192

#define BM 128
#define BN 128
#define BK 32
#define THREADS 256

#define ROWPITCH 80                    /* 32 bf16 = 64B data, padded to 80B */
#define TILE_B   (128 * ROWPITCH)      /* 10240 */
#define STAGE_B  (4 * TILE_B)          /* 40960: Ah, Al, Bh, Bl */
#define NSTAGE   3
#define SMEM_BYTES (NSTAGE * STAGE_B)  /* 122880 */

// ---------------- scratch (device globals; no allocation) ----------------
__device__ int   g_cnt[NEXP];
__device__ int   g_tok[NEXP * NTOK];
__device__ float g_wt [NEXP * NTOK];
__device__ __nv_bfloat16 g_xh [(size_t)NTOK * DIN];
__device__ __nv_bfloat16 g_xl [(size_t)NTOK * DIN];
__device__ __nv_bfloat16 g_hh [(size_t)NEXP * NTOK * DOUT];
__device__ __nv_bfloat16 g_hl [(size_t)NEXP * NTOK * DOUT];
__device__ __nv_bfloat16 g_W1Th[(size_t)NEXP * DIN * DOUT];
__device__ __nv_bfloat16 g_W1Tl[(size_t)NEXP * DIN * DOUT];
__device__ __nv_bfloat16 g_W2Th[(size_t)NEXP * DOUT * DOUT];
__device__ __nv_bfloat16 g_W2Tl[(size_t)NEXP * DOUT * DOUT];

// ---------------- helpers ----------------
__device__ __forceinline__ uint32_t smem_u32(const void* p) {
    uint32_t a;
    asm("{ .reg .u64 t; cvta.to.shared.u64 t, %1; cvt.u32.u64 %0, t; }" : "=r"(a) : "l"(p));
    return a;
}
__device__ __forceinline__ void cp_async16(uint32_t dst, const void* src) {
    asm volatile("cp.async.cg.shared.global [%0], [%1], 16;" :: "r"(dst), "l"(src) : "memory");
}
#define CP_COMMIT() asm volatile("cp.async.commit_group;" ::: "memory")
#define CP_WAIT1()  asm volatile("cp.async.wait_group 1;" ::: "memory")

__device__ __forceinline__ void mma_bf16(float* d, const uint32_t* a, const uint32_t* b) {
    asm volatile(
        "mma.sync.aligned.m16n8k16.row.col.f32.bf16.bf16.f32 "
        "{%0,%1,%2,%3},{%4,%5,%6,%7},{%8,%9},{%0,%1,%2,%3};"
        : "+f"(d[0]), "+f"(d[1]), "+f"(d[2]), "+f"(d[3])
        : "r"(a[0]), "r"(a[1]), "r"(a[2]), "r"(a[3]), "r"(b[0]), "r"(b[1]));
}
__device__ __forceinline__ void ldmx4(uint32_t* r, uint32_t addr) {
    asm volatile("ldmatrix.sync.aligned.m8n8.x4.shared.b16 {%0,%1,%2,%3}, [%4];"
                 : "=r"(r[0]), "=r"(r[1]), "=r"(r[2]), "=r"(r[3]) : "r"(addr));
}

// ---------------------------------------------------------------------------
__global__ void zero_kernel(float* __restrict__ out) {
    int i = blockIdx.x * blockDim.x + threadIdx.x;
    ((float4*)out)[i] = make_float4(0.f, 0.f, 0.f, 0.f);
    if (blockIdx.x == 0 && threadIdx.x < NEXP) g_cnt[threadIdx.x] = 0;
}

// ---------------------------------------------------------------------------
__global__ void gate_kernel(const float* __restrict__ x,
                            const float* __restrict__ Wg,
                            const float* __restrict__ bg) {
    int warp = (blockIdx.x * blockDim.x + threadIdx.x) >> 5;
    int lane = threadIdx.x & 31;
    if (warp >= NTOK) return;
    const float* xr = x + (size_t)warp * DIN;
    float acc[NEXP];
#pragma unroll
    for (int e = 0; e < NEXP; e++) acc[e] = 0.f;
    for (int kk = 0; kk < DIN / 32; kk++) {
        int k = kk * 32 + lane;
        float xv = xr[k];
        const float* wr = Wg + k * NEXP;
#pragma unroll
        for (int e = 0; e < NEXP; e++) acc[e] += xv * wr[e];
    }
#pragma unroll
    for (int e = 0; e < NEXP; e++)
#pragma unroll
        for (int o = 16; o > 0; o >>= 1)
            acc[e] += __shfl_xor_sync(0xffffffffu, acc[e], o);
    if (lane == 0) {
        float m = -1e30f;
#pragma unroll
        for (int e = 0; e < NEXP; e++) { acc[e] += bg[e]; m = fmaxf(m, acc[e]); }
        float s = 0.f;
#pragma unroll
        for (int e = 0; e < NEXP; e++) { acc[e] = expf(acc[e] - m); s += acc[e]; }
        float inv = 1.f / s;
        int e0 = 0, e1 = -1;
        float v0 = acc[0], v1 = -1.f;
#pragma unroll
        for (int e = 1; e < NEXP; e++) {
            float v = acc[e];
            if (v > v0)      { v1 = v0; e1 = e0; v0 = v; e0 = e; }
            else if (v > v1) { v1 = v;  e1 = e; }
        }
        int p0 = atomicAdd(&g_cnt[e0], 1);
        g_tok[e0 * NTOK + p0] = warp;  g_wt[e0 * NTOK + p0] = v0 * inv;
        int p1 = atomicAdd(&g_cnt[e1], 1);
        g_tok[e1 * NTOK + p1] = warp;  g_wt[e1 * NTOK + p1] = v1 * inv;
    }
}

// ---------------------------------------------------------------------------
__global__ void split_x_kernel(const float* __restrict__ x) {
    size_t i = ((size_t)blockIdx.x * blockDim.x + threadIdx.x) * 4;
    float4 v = *(const float4*)(x + i);
    __nv_bfloat16 h0 = __float2bfloat16(v.x), h1 = __float2bfloat16(v.y);
    __nv_bfloat16 h2 = __float2bfloat16(v.z), h3 = __float2bfloat16(v.w);
    __nv_bfloat16 l0 = __float2bfloat16(v.x - __bfloat162float(h0));
    __nv_bfloat16 l1 = __float2bfloat16(v.y - __bfloat162float(h1));
    __nv_bfloat16 l2 = __float2bfloat16(v.z - __bfloat162float(h2));
    __nv_bfloat16 l3 = __float2bfloat16(v.w - __bfloat162float(h3));
    *(__nv_bfloat162*)(g_xh + i)     = __halves2bfloat162(h0, h1);
    *(__nv_bfloat162*)(g_xh + i + 2) = __halves2bfloat162(h2, h3);
    *(__nv_bfloat162*)(g_xl + i)     = __halves2bfloat162(l0, l1);
    *(__nv_bfloat162*)(g_xl + i + 2) = __halves2bfloat162(l2, l3);
}

// ---------------------------------------------------------------------------
__global__ void transpose_split_kernel(const float* __restrict__ W,
                                       __nv_bfloat16* __restrict__ WTh,
                                       __nv_bfloat16* __restrict__ WTl) {
    __shared__ float t[32][33];
    int e = blockIdx.z;
    const float* Ws = W + ((size_t)e << 20);
    int x0 = blockIdx.x * 32, y0 = blockIdx.y * 32;
    int tx = threadIdx.x, ty = threadIdx.y;
#pragma unroll
    for (int i = 0; i < 32; i += 8)
        t[ty + i][tx] = Ws[(size_t)(y0 + ty + i) * 1024 + x0 + tx];
    __syncthreads();
#pragma unroll
    for (int i = 0; i < 32; i += 8) {
        float v = t[tx][ty + i];
        __nv_bfloat16 h = __float2bfloat16(v);
        __nv_bfloat16 l = __float2bfloat16(v - __bfloat162float(h));
        size_t o = ((size_t)e << 20) + (size_t)(x0 + ty + i) * 1024 + y0 + tx;
        WTh[o] = h;  WTl[o] = l;
    }
}

// ---------------------------------------------------------------------------
// bf16-split mma.sync GEMM with ldmatrix fragment loads.
// 128x128x32 tiles, 3-stage cp.async pipeline, 8 warps = 2(M) x 4(N),
// warp tile 64x32, 3 split terms (hh, hl, lh).
// ---------------------------------------------------------------------------
template <bool G2>
__global__ __launch_bounds__(THREADS, 1)
void moe_mma_kernel(const __nv_bfloat16* __restrict__ Wh,
                    const __nv_bfloat16* __restrict__ Wl,
                    const float* __restrict__ bias,
                    float* __restrict__ outp) {
    extern __shared__ char smem[];
    __shared__ int   s_tok[128];
    __shared__ float s_wt[128];
    __shared__ float s_bias[128];

    const int e   = blockIdx.z;
    const int cnt = g_cnt[e];
    const int m0  = blockIdx.y * BM;
    if (m0 >= cnt) return;
    const int n0  = blockIdx.x * BN;

    const int tid  = threadIdx.x;
    const int wid  = tid >> 5;
    const int lane = tid & 31;

    if (tid < 128) {
        int ok = (m0 + tid) < cnt;
        s_tok[tid] = ok ? g_tok[e * NTOK + m0 + tid] : 0;
        s_wt[tid]  = ok ? g_wt[e * NTOK + m0 + tid] : 0.f;
        s_bias[tid] = bias[e * 1024 + n0 + tid];
    }
    __syncthreads();

    // ---- per-thread cp.async geometry: tile = tid>>6 (Ah,Al,Bh,Bl) ----
    const int tile = tid >> 6;
    const int l64  = tid & 63;
    const int ch   = l64 & 3;            // 16B chunk within 64B row
    const __nv_bfloat16* gsrc[8];
    uint32_t sdst[8];
    const uint32_t sb = smem_u32(smem);
#pragma unroll
    for (int i = 0; i < 8; i++) {
        int r = i * 16 + (l64 >> 2);     // row 0..127
        const __nv_bfloat16* base;
        size_t rowidx;
        if (tile < 2) {
            if (G2) {
                base = tile ? g_hl : g_hh;
                rowidx = (size_t)e * NTOK + (size_t)((m0 + r < cnt) ? (m0 + r) : m0);
            } else {
                base = tile ? g_xl : g_xh;
                rowidx = (size_t)s_tok[r];
            }
        } else {
            base = (tile == 3) ? Wl : Wh;
            rowidx = ((size_t)e << 10) + (size_t)(n0 + r);  // e*1024 + row, in 1024-elem rows
        }
        gsrc[i] = base + rowidx * 1024 + ch * 8;
        sdst[i] = sb + tile * TILE_B + r * ROWPITCH + ch * 16;
    }

    auto issue = [&](int s, int c) {
        uint32_t so = (uint32_t)(s * STAGE_B);
        size_t ko = (size_t)c * BK;
#pragma unroll
        for (int i = 0; i < 8; i++)
            cp_async16(sdst[i] + so, gsrc[i] + ko);
    };

    float acc[4][4][4];
#pragma unroll
    for (int a = 0; a < 4; a++)
#pragma unroll
        for (int b = 0; b < 4; b++)
#pragma unroll
            for (int c = 0; c < 4; c++) acc[a][b][c] = 0.f;

    issue(0, 0); CP_COMMIT();
    issue(1, 1); CP_COMMIT();

    const int wm = wid >> 2;             // 0..1 -> m offset 64*wm
    const int wn = wid & 3;              // 0..3 -> n offset 32*wn

    // ldmatrix address templates (byte offsets within a tile, before stage/array)
    // A x4: groups g=lane>>3: (m0-7,k0),(m8-15,k0),(m0-7,k8),(m8-15,k8)
    const int aRow  = wm * 64 + (lane & 7) + ((lane >> 3) & 1) * 8;
    const int aKoff = ((lane >> 4) & 1) * 16;
    // B x4 (nf pair): (n0-7,k0),(n0-7,k8),(n8-15,k0),(n8-15,k8)
    const int bRow  = wn * 32 + (lane & 7) + ((lane >> 4) & 1) * 8;
    const int bKoff = ((lane >> 3) & 1) * 16;

    const int NITER = DIN / BK;          // 32
    for (int c = 0; c < NITER; c++) {
        const int s = c % NSTAGE;
        CP_WAIT1();
        __syncthreads();
        if (c + 2 < NITER) issue((c + 2) % NSTAGE, c + 2);
        CP_COMMIT();

        const uint32_t stg = sb + s * STAGE_B;
        const uint32_t Ah = stg;
        const uint32_t Al = stg + TILE_B;
        const uint32_t Bh = stg + 2 * TILE_B;
        const uint32_t Bl = stg + 3 * TILE_B;

#pragma unroll
        for (int ks = 0; ks < 2; ks++) {
            const uint32_t aoff = (uint32_t)(aRow * ROWPITCH + ks * 32 + aKoff);
            const uint32_t boff = (uint32_t)(bRow * ROWPITCH + ks * 32 + bKoff);
            uint32_t ah[4][4], al[4][4], bh[2][4], bl[2][4];
#pragma unroll
            for (int mf = 0; mf < 4; mf++) {
                ldmx4(ah[mf], Ah + aoff + mf * 16 * ROWPITCH);
                ldmx4(al[mf], Al + aoff + mf * 16 * ROWPITCH);
            }
#pragma unroll
            for (int np = 0; np < 2; np++) {
                ldmx4(bh[np], Bh + boff + np * 16 * ROWPITCH);
                ldmx4(bl[np], Bl + boff + np * 16 * ROWPITCH);
            }
#pragma unroll
            for (int mf = 0; mf < 4; mf++)
#pragma unroll
                for (int nf = 0; nf < 4; nf++)
                    mma_bf16(acc[mf][nf], ah[mf], &bh[nf >> 1][(nf & 1) * 2]);
#pragma unroll
            for (int mf = 0; mf < 4; mf++)
#pragma unroll
                for (int nf = 0; nf < 4; nf++)
                    mma_bf16(acc[mf][nf], ah[mf], &bl[nf >> 1][(nf & 1) * 2]);
#pragma unroll
            for (int mf = 0; mf < 4; mf++)
#pragma unroll
                for (int nf = 0; nf < 4; nf++)
                    mma_bf16(acc[mf][nf], al[mf], &bh[nf >> 1][(nf & 1) * 2]);
        }
    }

    // ---- epilogue: direct from registers (quads cover full 32B sectors) ----
    const int lr = lane >> 2;
    const int lc = (lane & 3) * 2;
#pragma unroll
    for (int mf = 0; mf < 4; mf++) {
#pragma unroll
        for (int nf = 0; nf < 4; nf++) {
            const float* d = acc[mf][nf];
            int col_l = wn * 32 + nf * 8 + lc;
            int colg  = n0 + col_l;
            float bb0 = s_bias[col_l], bb1 = s_bias[col_l + 1];
#pragma unroll
            for (int half = 0; half < 2; half++) {
                int row = wm * 64 + mf * 16 + lr + half * 8;  // local slot
                if (m0 + row >= cnt) continue;
                float v0 = d[half * 2]     + bb0;
                float v1 = d[half * 2 + 1] + bb1;
                if (!G2) {
                    v0 = fmaxf(v0, 0.f);  v1 = fmaxf(v1, 0.f);
                    __nv_bfloat16 h0 = __float2bfloat16(v0);
                    __nv_bfloat16 h1 = __float2bfloat16(v1);
                    __nv_bfloat16 l0 = __float2bfloat16(v0 - __bfloat162float(h0));
                    __nv_bfloat16 l1 = __float2bfloat16(v1 - __bfloat162float(h1));
                    size_t base = ((size_t)e * NTOK + m0 + row) * 1024 + colg;
                    *(__nv_bfloat162*)(g_hh + base) = __halves2bfloat162(h0, h1);
                    *(__nv_bfloat162*)(g_hl + base) = __halves2bfloat162(l0, l1);
                } else {
                    float w = s_wt[row];
                    float* o = outp + (size_t)s_tok[row] * 1024 + colg;
                    atomicAdd(o,     w * v0);
                    atomicAdd(o + 1, w * v1);
                }
            }
        }
    }
}

// ---------------------------------------------------------------------------
extern "C" void kernel_launch(void* const* d_in, const int* in_sizes, int n_in,
                              void* d_out, int out_size) {
    const float* x  = (const float*)d_in[0];
    const float* W1 = (const float*)d_in[1];
    const float* b1 = (const float*)d_in[2];
    const float* W2 = (const float*)d_in[3];
    const float* b2 = (const float*)d_in[4];
    const float* Wg = (const float*)d_in[5];
    const float* bg = (const float*)d_in[6];
    float* out = (float*)d_out;

    cudaFuncSetAttribute(moe_mma_kernel<false>,
                         cudaFuncAttributeMaxDynamicSharedMemorySize, SMEM_BYTES);
    cudaFuncSetAttribute(moe_mma_kernel<true>,
                         cudaFuncAttributeMaxDynamicSharedMemorySize, SMEM_BYTES);

    __nv_bfloat16 *w1th, *w1tl, *w2th, *w2tl;
    cudaGetSymbolAddress((void**)&w1th, g_W1Th);
    cudaGetSymbolAddress((void**)&w1tl, g_W1Tl);
    cudaGetSymbolAddress((void**)&w2th, g_W2Th);
    cudaGetSymbolAddress((void**)&w2tl, g_W2Tl);

    zero_kernel<<<(NTOK * DOUT) / 4 / 256, 256>>>(out);
    gate_kernel<<<(NTOK * 32) / 256, 256>>>(x, Wg, bg);
    split_x_kernel<<<(NTOK * DIN) / 4 / 256, 256>>>(x);

    dim3 tg(32, 32, NEXP);
    transpose_split_kernel<<<tg, dim3(32, 8)>>>(W1, w1th, w1tl);
    transpose_split_kernel<<<tg, dim3(32, 8)>>>(W2, w2th, w2tl);

    dim3 grid(DOUT / BN, NTOK / BM, NEXP);
    moe_mma_kernel<false><<<grid, THREADS, SMEM_BYTES>>>(w1th, w1tl, b1, nullptr);
    moe_mma_kernel<true><<<grid, THREADS, SMEM_BYTES>>>(w2th, w2tl, b2, out);
}